// round 1
// baseline (speedup 1.0000x reference)
#include <cuda_runtime.h>
#include <math.h>

// ---------------- device scratch (static, no allocations) ----------------
__device__ float g_buf1[4096ull * 2880];   // conv1+pool out [N,20,12,12]
__device__ float g_feat[4096ull * 800];    // conv2+pool out flattened [N,800]
__device__ float g_h[4096ull * 50];        // fc out [N,50]
__device__ float g_G[4096ull * 4096];      // gram h h^T
__device__ float g_sq[4096];               // diag of G
__device__ unsigned g_hist[256];
__device__ float g_thr;
__device__ unsigned g_E;
__device__ float g_agg[4096ull * 50];
__device__ float g_deg[4096];
__device__ float g_Z[4096ull * 50];
__device__ float g_colsum[50];

// ---------------- init ----------------
__global__ void k_init() {
    int t = threadIdx.x;
    if (t < 256) g_hist[t] = 0u;
    if (t == 0) g_E = 0u;
}

// ---------------- conv1 (1->20, 5x5 VALID) + relu + maxpool2 ----------------
__global__ __launch_bounds__(256) void k_conv1(const float* __restrict__ x,
                                               const float* __restrict__ w,
                                               const float* __restrict__ b) {
    __shared__ float s_in[784];
    __shared__ float s_w[500];
    __shared__ float s_b[20];
    int img = blockIdx.x;
    int tid = threadIdx.x;
    const float* xin = x + (size_t)img * 784;
    for (int t = tid; t < 784; t += 256) s_in[t] = xin[t];
    for (int t = tid; t < 500; t += 256) s_w[t] = w[t];
    if (tid < 20) s_b[tid] = b[tid];
    __syncthreads();
    // work item = (channel, 2x2-pooled quadrant) -> 4x4 conv region, 8x8 input window
    #pragma unroll 1
    for (int idx = tid; idx < 20 * 36; idx += 256) {
        int c = idx / 36;
        int q = idx % 36;
        int qy = q / 6, qx = q % 6;
        int y0 = qy * 4, x0 = qx * 4;
        float wreg[25];
        #pragma unroll
        for (int k = 0; k < 25; k++) wreg[k] = s_w[c * 25 + k];
        float in[8][8];
        #pragma unroll
        for (int r = 0; r < 8; r++)
            #pragma unroll
            for (int cc = 0; cc < 8; cc++)
                in[r][cc] = s_in[(y0 + r) * 28 + (x0 + cc)];
        float acc[4][4];
        #pragma unroll
        for (int oy = 0; oy < 4; oy++)
            #pragma unroll
            for (int ox = 0; ox < 4; ox++) {
                float a = s_b[c];
                #pragma unroll
                for (int ky = 0; ky < 5; ky++)
                    #pragma unroll
                    for (int kx = 0; kx < 5; kx++)
                        a = fmaf(in[oy + ky][ox + kx], wreg[ky * 5 + kx], a);
                acc[oy][ox] = a;
            }
        #pragma unroll
        for (int ry = 0; ry < 2; ry++)
            #pragma unroll
            for (int rx = 0; rx < 2; rx++) {
                float m = fmaxf(fmaxf(acc[2*ry][2*rx], acc[2*ry][2*rx+1]),
                                fmaxf(acc[2*ry+1][2*rx], acc[2*ry+1][2*rx+1]));
                m = fmaxf(m, 0.0f);
                int py = qy * 2 + ry, px = qx * 2 + rx;
                g_buf1[(size_t)img * 2880 + c * 144 + py * 12 + px] = m;
            }
    }
}

// ---------------- conv2 (20->50, 5x5 VALID) + relu + maxpool2 ----------------
__global__ __launch_bounds__(256) void k_conv2(const float* __restrict__ w,
                                               const float* __restrict__ b) {
    extern __shared__ float sm[];
    float* s_in = sm;            // 2880
    float* s_w  = sm + 2880;     // 25000
    float* s_b  = sm + 27880;    // 50
    int img = blockIdx.x;
    int tid = threadIdx.x;
    const float* xin = g_buf1 + (size_t)img * 2880;
    for (int t = tid; t < 2880; t += 256) s_in[t] = xin[t];
    for (int t = tid; t < 25000; t += 256) s_w[t] = w[t];
    if (tid < 50) s_b[tid] = b[tid];
    __syncthreads();
    // 50 channels * 4 quadrants = 200 work items, one per thread
    int idx = tid;
    if (idx < 200) {
        int c = idx / 4;
        int q = idx % 4;
        int qy = q / 2, qx = q % 2;
        int y0 = qy * 4, x0 = qx * 4;
        float acc[16];
        #pragma unroll
        for (int k = 0; k < 16; k++) acc[k] = s_b[c];
        #pragma unroll 1
        for (int ic = 0; ic < 20; ic++) {
            float wreg[25];
            #pragma unroll
            for (int k = 0; k < 25; k++) wreg[k] = s_w[c * 500 + ic * 25 + k];
            float in[8][8];
            #pragma unroll
            for (int r = 0; r < 8; r++)
                #pragma unroll
                for (int cc = 0; cc < 8; cc++)
                    in[r][cc] = s_in[ic * 144 + (y0 + r) * 12 + (x0 + cc)];
            #pragma unroll
            for (int oy = 0; oy < 4; oy++)
                #pragma unroll
                for (int ox = 0; ox < 4; ox++) {
                    float a = acc[oy * 4 + ox];
                    #pragma unroll
                    for (int ky = 0; ky < 5; ky++)
                        #pragma unroll
                        for (int kx = 0; kx < 5; kx++)
                            a = fmaf(in[oy + ky][ox + kx], wreg[ky * 5 + kx], a);
                    acc[oy * 4 + ox] = a;
                }
        }
        #pragma unroll
        for (int ry = 0; ry < 2; ry++)
            #pragma unroll
            for (int rx = 0; rx < 2; rx++) {
                float m = fmaxf(fmaxf(acc[(2*ry)*4 + 2*rx], acc[(2*ry)*4 + 2*rx+1]),
                                fmaxf(acc[(2*ry+1)*4 + 2*rx], acc[(2*ry+1)*4 + 2*rx+1]));
                m = fmaxf(m, 0.0f);
                int py = qy * 2 + ry, px = qx * 2 + rx;
                g_feat[(size_t)img * 800 + c * 16 + py * 4 + px] = m;
            }
    }
}

// ---------------- fc 800->50 + relu ----------------
__global__ __launch_bounds__(64) void k_fc(const float* __restrict__ w,
                                           const float* __restrict__ b) {
    __shared__ float s_in[800];
    int img = blockIdx.x, tid = threadIdx.x;
    const float* xin = g_feat + (size_t)img * 800;
    for (int t = tid; t < 800; t += 64) s_in[t] = xin[t];
    __syncthreads();
    if (tid < 50) {
        const float* wr = w + tid * 800;
        float a0 = 0.f, a1 = 0.f, a2 = 0.f, a3 = 0.f;
        for (int k = 0; k < 800; k += 4) {
            a0 = fmaf(s_in[k],     wr[k],     a0);
            a1 = fmaf(s_in[k + 1], wr[k + 1], a1);
            a2 = fmaf(s_in[k + 2], wr[k + 2], a2);
            a3 = fmaf(s_in[k + 3], wr[k + 3], a3);
        }
        float hv = fmaxf((a0 + a1) + (a2 + a3) + b[tid], 0.0f);
        g_h[(size_t)img * 50 + tid] = hv;
    }
}

// ---------------- gram G = h h^T ----------------
__global__ __launch_bounds__(256) void k_gram() {
    __shared__ float As[64][51];
    __shared__ float Bs[64][51];
    int i0 = blockIdx.y * 64, j0 = blockIdx.x * 64;
    int tid = threadIdx.x;
    for (int t = tid; t < 64 * 50; t += 256) {
        int r = t / 50, c = t % 50;
        As[r][c] = g_h[(size_t)(i0 + r) * 50 + c];
        Bs[r][c] = g_h[(size_t)(j0 + r) * 50 + c];
    }
    __syncthreads();
    int ty = tid / 16, tx = tid % 16;
    float acc[4][4] = {};
    for (int k = 0; k < 50; k++) {
        float a[4], bb[4];
        #pragma unroll
        for (int u = 0; u < 4; u++) a[u] = As[ty * 4 + u][k];
        #pragma unroll
        for (int v = 0; v < 4; v++) bb[v] = Bs[tx * 4 + v][k];
        #pragma unroll
        for (int u = 0; u < 4; u++)
            #pragma unroll
            for (int v = 0; v < 4; v++)
                acc[u][v] = fmaf(a[u], bb[v], acc[u][v]);
    }
    #pragma unroll
    for (int u = 0; u < 4; u++)
        #pragma unroll
        for (int v = 0; v < 4; v++)
            g_G[(size_t)(i0 + ty * 4 + u) * 4096 + (j0 + tx * 4 + v)] = acc[u][v];
}

__global__ void k_sq() {
    int i = blockIdx.x * 256 + threadIdx.x;
    if (i < 4096) g_sq[i] = g_G[(size_t)i * 4097];
}

// ---------------- distance histogram over 256 candidate radii ----------------
__global__ __launch_bounds__(256) void k_hist() {
    __shared__ unsigned s_hist[256];
    s_hist[threadIdx.x] = 0u;
    __syncthreads();
    int i = blockIdx.x;
    float sqi = g_sq[i];
    const float* Grow = g_G + (size_t)i * 4096;
    for (int j = threadIdx.x; j < 4096; j += 256) {
        if (j == i) continue;
        float g = Grow[j];
        float d = sqrtf(fmaxf(sqi - 2.0f * g + g_sq[j], 0.0f));
        // b0 = smallest k such that (3.5 + 0.5k) > d  (exact fp32 semantics)
        float t = (d - 3.5f) * 2.0f;
        int b0 = (int)floorf(t) + 1;
        if (b0 < 0) b0 = 0;
        if (b0 > 256) b0 = 256;
        while (b0 > 0 && (3.5f + 0.5f * (float)(b0 - 1)) > d) b0--;
        while (b0 < 256 && !((3.5f + 0.5f * (float)b0) > d)) b0++;
        if (b0 < 256) atomicAdd(&s_hist[b0], 1u);
    }
    __syncthreads();
    unsigned v = s_hist[threadIdx.x];
    if (v) atomicAdd(&g_hist[threadIdx.x], v);
}

// ---------------- prefix scan -> pick threshold ----------------
__global__ void k_scan() {
    __shared__ unsigned s_h[256];
    __shared__ int s_min;
    int k = threadIdx.x;
    s_h[k] = g_hist[k];
    if (k == 0) s_min = 256;
    __syncthreads();
    unsigned cnt = 0;
    for (int b = 0; b <= k; b++) cnt += s_h[b];
    if ((float)cnt >= 409.6f) atomicMin(&s_min, k);  // 0.1 * 4096
    __syncthreads();
    if (k == 0) {
        int kk = (s_min >= 256) ? 0 : s_min;   // argmax of all-false -> 0
        g_thr = 3.5f + 0.5f * (float)kk;
    }
}

// ---------------- agg = A @ h, deg, E (mask recomputed from G) ----------------
__global__ __launch_bounds__(256) void k_agg() {
    __shared__ float h_s[128][51];
    __shared__ float sq_s[128];
    int warp = threadIdx.x >> 5, lane = threadIdx.x & 31;
    int row = blockIdx.x * 8 + warp;
    float thr = g_thr;
    float sqi = g_sq[row];
    float acc[50];
    #pragma unroll
    for (int c = 0; c < 50; c++) acc[c] = 0.0f;
    int deg = 0;
    const float* Grow = g_G + (size_t)row * 4096;
    for (int jt = 0; jt < 4096; jt += 128) {
        __syncthreads();
        for (int t = threadIdx.x; t < 128 * 50; t += 256) {
            int r = t / 50, c = t % 50;
            h_s[r][c] = g_h[(size_t)(jt + r) * 50 + c];
        }
        if (threadIdx.x < 128) sq_s[threadIdx.x] = g_sq[jt + threadIdx.x];
        __syncthreads();
        #pragma unroll
        for (int u = 0; u < 4; u++) {
            int jj = lane + u * 32;
            int j = jt + jj;
            float g = Grow[j];
            float d = sqrtf(fmaxf(sqi - 2.0f * g + sq_s[jj], 0.0f));
            if (d < thr && j != row) {
                deg++;
                #pragma unroll
                for (int c = 0; c < 50; c++) acc[c] += h_s[jj][c];
            }
        }
    }
    #pragma unroll
    for (int c = 0; c < 50; c++) {
        float v = acc[c];
        #pragma unroll
        for (int off = 16; off > 0; off >>= 1) v += __shfl_down_sync(0xffffffffu, v, off);
        if (lane == 0) g_agg[(size_t)row * 50 + c] = v;
    }
    #pragma unroll
    for (int off = 16; off > 0; off >>= 1) deg += __shfl_down_sync(0xffffffffu, deg, off);
    if (lane == 0) {
        g_deg[row] = (float)deg;
        atomicAdd(&g_E, (unsigned)deg);
    }
}

// ---------------- Z = leaky((agg/deg) Wrel^T + brel + h Wroot^T) ----------------
__global__ __launch_bounds__(64) void k_z(const float* __restrict__ wrel,
                                          const float* __restrict__ brel,
                                          const float* __restrict__ wroot) {
    __shared__ float s_m[50], s_h[50];
    int i = blockIdx.x, tid = threadIdx.x;
    if (tid < 50) {
        float dg = fmaxf(g_deg[i], 1.0f);
        s_m[tid] = g_agg[(size_t)i * 50 + tid] / dg;
        s_h[tid] = g_h[(size_t)i * 50 + tid];
    }
    __syncthreads();
    if (tid < 50) {
        float a = brel[tid];
        const float* w1 = wrel + tid * 50;
        const float* w2 = wroot + tid * 50;
        #pragma unroll
        for (int c = 0; c < 50; c++)
            a = fmaf(s_m[c], w1[c], fmaf(s_h[c], w2[c], a));
        float z = (a >= 0.0f) ? a : 0.01f * a;
        g_Z[(size_t)i * 50 + tid] = z;
    }
}

// ---------------- column sums of Z (s = softmax over dim-1 == ones) ----------------
__global__ __launch_bounds__(256) void k_colsum() {
    __shared__ float red[256];
    int c = blockIdx.x, tid = threadIdx.x;
    float s = 0.0f;
    for (int i = tid; i < 4096; i += 256) s += g_Z[(size_t)i * 50 + c];
    red[tid] = s;
    __syncthreads();
    for (int w = 128; w > 0; w >>= 1) {
        if (tid < w) red[tid] += red[tid + w];
        __syncthreads();
    }
    if (tid == 0) g_colsum[c] = red[0];
}

// ---------------- final head ----------------
__global__ void k_final(const float* __restrict__ wrel, const float* __restrict__ brel,
                        const float* __restrict__ wroot,
                        const float* __restrict__ l1w, const float* __restrict__ l1b,
                        const float* __restrict__ l2w, const float* __restrict__ l2b,
                        float* __restrict__ out, int out_size) {
    __shared__ float xp0[50];
    __shared__ float xp[50];
    __shared__ float v1[25];
    int tid = threadIdx.x;
    if (tid < 50) xp0[tid] = g_colsum[tid];
    __syncthreads();
    float Ef = (float)g_E;
    float degv = fmaxf(Ef, 1.0f);
    if (tid < 50) {
        float a = brel[tid];
        for (int c = 0; c < 50; c++) {
            float m = (Ef * xp0[c]) / degv;   // (adjp * x) / clip(adjp,1)
            a = fmaf(m, wrel[tid * 50 + c], fmaf(xp0[c], wroot[tid * 50 + c], a));
        }
        xp[tid] = (a >= 0.0f) ? a : 0.01f * a;
    }
    __syncthreads();
    if (tid < 25) {
        float a = l1b[tid];
        for (int c = 0; c < 50; c++) a = fmaf(xp[c], l1w[tid * 50 + c], a);
        v1[tid] = (a >= 0.0f) ? a : 0.01f * a;
    }
    __syncthreads();
    if (tid == 0) {
        float v2[2];
        for (int k = 0; k < 2; k++) {
            float a = l2b[k];
            for (int c = 0; c < 25; c++) a = fmaf(v1[c], l2w[k * 25 + c], a);
            v2[k] = (a >= 0.0f) ? a : 0.01f * a;
        }
        float mx = fmaxf(v2[0], v2[1]);
        float e0 = expf(v2[0] - mx), e1 = expf(v2[1] - mx);
        float inv = 1.0f / (e0 + e1);
        float p0 = e0 * inv, p1 = e1 * inv;
        int am = (p1 > p0) ? 1 : 0;           // ties -> index 0 (argmax semantics)
        float pm = fmaxf(p0, p1);
        unsigned E = g_E;
        float l1 = sqrtf((float)(16777216u - E)) / 16777216.0f;
        if (out_size > 0) out[0] = pm;
        if (out_size > 1) out[1] = (float)am;
        if (out_size > 2) out[2] = l1;
    }
}

// ---------------- launch ----------------
extern "C" void kernel_launch(void* const* d_in, const int* in_sizes, int n_in,
                              void* d_out, int out_size) {
    (void)in_sizes; (void)n_in;
    const float* x        = (const float*)d_in[0];
    const float* conv1_w  = (const float*)d_in[1];
    const float* conv1_b  = (const float*)d_in[2];
    const float* conv2_w  = (const float*)d_in[3];
    const float* conv2_b  = (const float*)d_in[4];
    const float* fc_w     = (const float*)d_in[5];
    const float* fc_b     = (const float*)d_in[6];
    const float* erel_w   = (const float*)d_in[7];
    const float* erel_b   = (const float*)d_in[8];
    const float* eroot_w  = (const float*)d_in[9];
    // d_in[10..14]: pool_* / mlp_* — provably dead (softmax over size-1 axis == 1)
    const float* lin1_w   = (const float*)d_in[15];
    const float* lin1_b   = (const float*)d_in[16];
    const float* lin2_w   = (const float*)d_in[17];
    const float* lin2_b   = (const float*)d_in[18];
    float* out = (float*)d_out;

    const int SMEM2 = (2880 + 25000 + 50) * 4;  // 111720 B
    cudaFuncSetAttribute(k_conv2, cudaFuncAttributeMaxDynamicSharedMemorySize, SMEM2);

    k_init<<<1, 256>>>();
    k_conv1<<<4096, 256>>>(x, conv1_w, conv1_b);
    k_conv2<<<4096, 256, SMEM2>>>(conv2_w, conv2_b);
    k_fc<<<4096, 64>>>(fc_w, fc_b);
    k_gram<<<dim3(64, 64), 256>>>();
    k_sq<<<16, 256>>>();
    k_hist<<<4096, 256>>>();
    k_scan<<<1, 256>>>();
    k_agg<<<512, 256>>>();
    k_z<<<4096, 64>>>(erel_w, erel_b, eroot_w);
    k_colsum<<<50, 256>>>();
    k_final<<<1, 64>>>(erel_w, erel_b, eroot_w, lin1_w, lin1_b, lin2_w, lin2_b, out, out_size);
}